// round 10
// baseline (speedup 1.0000x reference)
#include <cuda_runtime.h>
#include <cuda_bf16.h>
#include <cstdint>

// Deformable Conv3d via portable HMMA (mma.sync.m16n8k16.bf16, hi/lo split).
// R10: producer/consumer warp specialization.
//   warps 8-15: producers — sample 16 points each per tap (factored trilinear,
//               AND-wrap addressing), write bf16 hi/lo A tiles (double-buffered)
//   warps 0-7:  consumers — each owns a 32x32 D-tile (2 m16 tiles x n32),
//               ldmatrix A/B fragments + 96 mma per tap, fp32 reg accumulators
//   sync: one named barrier per tap among each {2 prod, 2 cons} 128-thread
//   group; B weight images staged per 10-tap phase (block-wide).

namespace {
constexpr int B_ = 2, CIN_ = 64, COUT_ = 64, D_ = 8, H_ = 32, W_ = 32, K_ = 27;
constexpr int P_ = D_ * H_ * W_;              // 8192
constexpr int MTILE = 128;
constexpr int THREADS = 512;
constexpr int NBLK = (B_ * P_) / MTILE;       // 128
constexpr int PH   = 10;                      // taps per B phase (10,10,7)

constexpr int SM_B     = 2 * 32768;           // A: [buf][hi 16K | lo 16K]
constexpr int SM_TOTAL = SM_B + PH * 16384;   // 229376 (224KB)
constexpr unsigned FULL = 0xffffffffu;
}

__device__ __align__(256) float g_xT[B_ * P_ * CIN_];            // channels-last x
// B images, ldmatrix layout: [kt][j(8)][ks(4)][hl(2)][kh(2)][row(8)][16B]
__device__ __align__(256) unsigned char g_wB[K_ * 16384];

// ---------------- helpers ----------------
__device__ __forceinline__ uint32_t smem_u32(const void* p) {
    uint32_t a;
    asm("{ .reg .u64 t; cvta.to.shared.u64 t, %1; cvt.u32.u64 %0, t; }"
        : "=r"(a) : "l"(p));
    return a;
}
__device__ __forceinline__ uint32_t bf16x2(float hi_elem, float lo_elem) {
    uint32_t r;
    asm("cvt.rn.bf16x2.f32 %0, %1, %2;" : "=r"(r) : "f"(hi_elem), "f"(lo_elem));
    return r;
}
__device__ __forceinline__ void ldm_x4(uint32_t* r, uint32_t addr) {
    asm volatile("ldmatrix.sync.aligned.m8n8.x4.shared.b16 {%0,%1,%2,%3}, [%4];"
                 : "=r"(r[0]), "=r"(r[1]), "=r"(r[2]), "=r"(r[3]) : "r"(addr));
}
__device__ __forceinline__ void mma_bf16(float* c, const uint32_t* a,
                                         const uint32_t* b) {
    asm volatile(
        "mma.sync.aligned.m16n8k16.row.col.f32.bf16.bf16.f32 "
        "{%0,%1,%2,%3}, {%4,%5,%6,%7}, {%8,%9}, {%0,%1,%2,%3};"
        : "+f"(c[0]), "+f"(c[1]), "+f"(c[2]), "+f"(c[3])
        : "r"(a[0]), "r"(a[1]), "r"(a[2]), "r"(a[3]), "r"(b[0]), "r"(b[1]));
}
__device__ __forceinline__ void bar_group(int id) {
    asm volatile("bar.sync %0, 128;" :: "r"(id) : "memory");
}

// ---------------- prep ----------------
__global__ void prep_kernel(const float* __restrict__ x,
                            const float* __restrict__ w) {
    const int stride = gridDim.x * blockDim.x;
    const int tid = blockIdx.x * blockDim.x + threadIdx.x;

    for (int i = tid; i < B_ * CIN_ * P_; i += stride) {
        int s = i % P_;
        int c = (i / P_) % CIN_;
        int b = i / (P_ * CIN_);
        g_xT[(b * P_ + s) * CIN_ + c] = x[i];
    }

    for (int i = tid; i < K_ * COUT_ * CIN_; i += stride) {
        int c  = i % CIN_;
        int n  = (i / CIN_) % COUT_;
        int kt = i / (CIN_ * COUT_);
        float v = w[(n * CIN_ + c) * K_ + kt];
        __nv_bfloat16 hi = __float2bfloat16(v);
        __nv_bfloat16 lo = __float2bfloat16(v - __bfloat162float(hi));
        int j = n >> 3, r = n & 7, ks = c >> 4, kh = (c >> 3) & 1, col = c & 7;
        size_t base = (size_t)kt * 16384 + (size_t)j * 2048 + (size_t)ks * 512;
        size_t off  = (size_t)kh * 128 + (size_t)r * 16 + (size_t)col * 2;
        *reinterpret_cast<__nv_bfloat16*>(g_wB + base + off)       = hi;
        *reinterpret_cast<__nv_bfloat16*>(g_wB + base + 256 + off) = lo;
    }
}

// ---------------- main ----------------
__global__ __launch_bounds__(THREADS, 1)
void deform_hmma_kernel(const float* __restrict__ offset,
                        const float* __restrict__ bias,
                        float* __restrict__ out) {
    extern __shared__ __align__(1024) char smem[];
    const uint32_t sb = smem_u32(smem);

    const int tid  = threadIdx.x;
    const int lane = tid & 31;
    const int warp = tid >> 5;               // 0-7 consumers, 8-15 producers
    const int blk  = blockIdx.x;
    const int b    = blk >> 6;
    const int p0   = (blk & 63) * MTILE;

    const float* offB = offset + (size_t)b * 3 * K_ * P_;
    const char*  xb   = reinterpret_cast<const char*>(g_xT + (size_t)b * P_ * CIN_);

    const bool is_prod = warp >= 8;

    // ---------- producer state ----------
    const int wp   = warp - 8;               // 0..7
    const int half = lane >> 4;
    const int c4   = lane & 15;
    const int pl_base = wp * 16;             // 16 points per producer
    const char* base2 = xb + (uint32_t)(c4 << 4);
    const int grp_p = (wp >> 1) + 1;         // barrier id 1..4

    // ---------- consumer state ----------
    const int mt = warp >> 1, nt = warp & 1; // 32-row, 32-col tile
    const int rowA0 = mt * 32 + (lane & 15);
    const uint32_t aXor0 = (uint32_t)((rowA0 & 7) << 4);
    const uint32_t aKh   = (uint32_t)((lane >> 4) << 4);
    const uint32_t bLane = (uint32_t)(((lane >> 3) << 7) + ((lane & 7) << 4));
    const int grp_c = mt + 1;                // matches producers 2mt, 2mt+1

    float acc[2][4][4];
#pragma unroll
    for (int tl = 0; tl < 2; tl++)
#pragma unroll
        for (int j = 0; j < 4; j++)
#pragma unroll
            for (int q = 0; q < 4; q++) acc[tl][j][q] = 0.f;

    // ---- producer sampling of one tap into buffer ----
    auto sample_tap = [&](int kt, int buf) {
        char* AhP = smem + buf * 32768;
        char* AlP = AhP + 16384;
        const int kd = kt / 9, kh3 = (kt / 3) % 3, kw3 = kt % 3;
        const float* offk = offB + 3 * kt * P_;
#pragma unroll 4
        for (int i = 0; i < 16; i++) {
            const int pl = pl_base + i;
            const int p  = p0 + pl;
            const int od = p >> 10, oh = (p >> 5) & 31, ow = p & 31;

            float zd = (float)(od - 1 + kd)  + __ldg(offk + p);
            float zh = (float)(oh - 1 + kh3) + __ldg(offk + P_ + p);
            float zw = (float)(ow - 1 + kw3) + __ldg(offk + 2 * P_ + p);

            float fd = floorf(zd); int d0 = (int)fd; float rd = zd - fd;
            float fh = floorf(zh); int h0 = (int)fh; float rh = zh - fh;
            float fw = floorf(zw); int w0 = (int)fw; float rw = zw - fw;

            float wd = half ? (((unsigned)(d0 + 1) < (unsigned)D_) ? rd : 0.f)
                            : (((unsigned)d0 < (unsigned)D_) ? 1.f - rd : 0.f);
            float wh0 = ((unsigned)h0       < (unsigned)H_) ? 1.f - rh : 0.f;
            float wh1 = ((unsigned)(h0 + 1) < (unsigned)H_) ? rh       : 0.f;
            float ww0 = ((unsigned)w0       < (unsigned)W_) ? 1.f - rw : 0.f;
            float ww1 = ((unsigned)(w0 + 1) < (unsigned)W_) ? rw       : 0.f;

            const int s0 = (d0 + half) * 1024 + h0 * 32 + w0;
            const uint32_t i0 = ((uint32_t)s0        & 8191u) << 8;
            const uint32_t i1 = ((uint32_t)(s0 + 1)  & 8191u) << 8;
            const uint32_t i2 = ((uint32_t)(s0 + 32) & 8191u) << 8;
            const uint32_t i3 = ((uint32_t)(s0 + 33) & 8191u) << 8;

            const float wdh0 = wd * wh0, wdh1 = wd * wh1;
            const float g0 = wdh0 * ww0, g1 = wdh0 * ww1;
            const float g2 = wdh1 * ww0, g3 = wdh1 * ww1;

            float4 v0 = __ldg(reinterpret_cast<const float4*>(base2 + i0));
            float4 v1 = __ldg(reinterpret_cast<const float4*>(base2 + i1));
            float4 v2 = __ldg(reinterpret_cast<const float4*>(base2 + i2));
            float4 v3 = __ldg(reinterpret_cast<const float4*>(base2 + i3));

            float ax = g0 * v0.x + g1 * v1.x + g2 * v2.x + g3 * v3.x;
            float ay = g0 * v0.y + g1 * v1.y + g2 * v2.y + g3 * v3.y;
            float az = g0 * v0.z + g1 * v1.z + g2 * v2.z + g3 * v3.z;
            float aw = g0 * v0.w + g1 * v1.w + g2 * v2.w + g3 * v3.w;

            ax += __shfl_down_sync(FULL, ax, 16);
            ay += __shfl_down_sync(FULL, ay, 16);
            az += __shfl_down_sync(FULL, az, 16);
            aw += __shfl_down_sync(FULL, aw, 16);

            if (half == 0) {
                uint32_t h01 = bf16x2(ay, ax);       // hi=ch+1, lo=ch+0
                uint32_t h23 = bf16x2(aw, az);
                float hx = __uint_as_float(h01 << 16);
                float hy = __uint_as_float(h01 & 0xffff0000u);
                float hz = __uint_as_float(h23 << 16);
                float hww = __uint_as_float(h23 & 0xffff0000u);
                uint32_t l01 = bf16x2(ay - hy, ax - hx);
                uint32_t l23 = bf16x2(aw - hww, az - hz);
                const uint32_t so = (uint32_t)(pl * 128 + ((c4 * 8) ^ ((pl & 7) << 4)));
                *reinterpret_cast<uint2*>(AhP + so) = make_uint2(h01, h23);
                *reinterpret_cast<uint2*>(AlP + so) = make_uint2(l01, l23);
            }
        }
    };

    // ---- prologue: producers fill tap 0 into buf 0 ----
    if (is_prod) sample_tap(0, 0);
    bar_group(is_prod ? grp_p : grp_c);

#pragma unroll 1
    for (int kt = 0; kt < K_; kt++) {
        const int buf = kt & 1;
        const int t = kt % PH;

        // B phase staging (block-wide, 3x per kernel)
        if (t == 0) {
            __syncthreads();
            const int ph_len = (kt + PH <= K_) ? PH : (K_ - kt);
            const uint4* src = reinterpret_cast<const uint4*>(g_wB + (size_t)kt * 16384);
            uint4* dst = reinterpret_cast<uint4*>(smem + SM_B);
            const int nvec = ph_len * 1024;
            for (int i = tid; i < nvec; i += THREADS)
                dst[i] = __ldg(&src[i]);
            __syncthreads();
        }

        if (is_prod) {
            // sample next tap into the other buffer
            if (kt + 1 < K_) sample_tap(kt + 1, buf ^ 1);
            bar_group(grp_p);
        } else {
            // ---- consumer: mma tap kt from buf ----
            const uint32_t AhB = sb + buf * 32768;
            const uint32_t AlB = AhB + 16384;
            const uint32_t Bt  = sb + SM_B + t * 16384;
#pragma unroll
            for (int ks = 0; ks < 4; ks++) {
                const uint32_t kterm = (uint32_t)(ks * 32) + aKh;
                uint32_t ah0[4], al0[4], ah1[4], al1[4];
                const uint32_t aoff0 = (uint32_t)(rowA0 * 128) + (kterm ^ aXor0);
                const uint32_t aoff1 = aoff0 + 16 * 128;   // rows +16, same swizzle
                ldm_x4(ah0, AhB + aoff0);
                ldm_x4(al0, AlB + aoff0);
                ldm_x4(ah1, AhB + aoff1);
                ldm_x4(al1, AlB + aoff1);
#pragma unroll
                for (int j = 0; j < 4; j++) {
                    uint32_t bb[4];      // hi-b0, hi-b1, lo-b0, lo-b1
                    ldm_x4(bb, Bt + (uint32_t)((nt * 4 + j) * 2048 + ks * 512) + bLane);
                    mma_bf16(acc[0][j], ah0, &bb[0]);
                    mma_bf16(acc[0][j], al0, &bb[0]);
                    mma_bf16(acc[0][j], ah0, &bb[2]);
                    mma_bf16(acc[1][j], ah1, &bb[0]);
                    mma_bf16(acc[1][j], al1, &bb[0]);
                    mma_bf16(acc[1][j], ah1, &bb[2]);
                }
            }
            bar_group(grp_c);
        }
    }

    // ---- epilogue: consumers scatter D fragments + bias ----
    if (!is_prod) {
        const int m = lane >> 2;
#pragma unroll
        for (int tl = 0; tl < 2; tl++) {
            const int p = p0 + mt * 32 + tl * 16 + m;
#pragma unroll
            for (int j = 0; j < 4; j++) {
                const int n = nt * 32 + j * 8 + 2 * (lane & 3);
                const float bv0 = __ldg(&bias[n]);
                const float bv1 = __ldg(&bias[n + 1]);
                float* o0 = out + ((size_t)(b * COUT_ + n)) * P_ + p;
                o0[0]      = acc[tl][j][0] + bv0;
                o0[P_]     = acc[tl][j][1] + bv1;
                o0[8]      = acc[tl][j][2] + bv0;
                o0[P_ + 8] = acc[tl][j][3] + bv1;
            }
        }
    }
}

extern "C" void kernel_launch(void* const* d_in, const int* in_sizes, int n_in,
                              void* d_out, int out_size) {
    const float* x      = (const float*)d_in[0];
    const float* offset = (const float*)d_in[1];
    const float* weight = (const float*)d_in[2];
    const float* bias   = (const float*)d_in[3];
    float* out = (float*)d_out;

    cudaFuncSetAttribute(deform_hmma_kernel,
                         cudaFuncAttributeMaxDynamicSharedMemorySize, SM_TOTAL);
    prep_kernel<<<256, 256>>>(x, weight);
    deform_hmma_kernel<<<NBLK, THREADS, SM_TOTAL>>>(offset, bias, out);
}

// round 11
// speedup vs baseline: 1.9369x; 1.9369x over previous
#include <cuda_runtime.h>
#include <cuda_bf16.h>
#include <cstdint>

// Deformable Conv3d via portable HMMA (mma.sync.m16n8k16.bf16, hi/lo split).
// R11: R8 structure, but MTILE=64 / 256 threads / 256 blocks -> 2 independent
//      blocks per SM (barrier stalls of one block filled by the other).
//      B operands via fragment-ordered global LDG (R7 layout): no B smem, no
//      block-wide __syncthreads anywhere; only per-pair named barriers.

namespace {
constexpr int B_ = 2, CIN_ = 64, COUT_ = 64, D_ = 8, H_ = 32, W_ = 32, K_ = 27;
constexpr int P_ = D_ * H_ * W_;              // 8192
constexpr int MTILE = 64;
constexpr int THREADS = 256;
constexpr int NBLK = (B_ * P_) / MTILE;       // 256

// dynamic smem: A only, [buf][hi 8K | lo 8K]
constexpr int SM_TOTAL = 2 * 16384;           // 32768
constexpr unsigned FULL = 0xffffffffu;
}

__device__ __align__(256) float g_xT[B_ * P_ * CIN_];           // channels-last x
__device__ __align__(256) uint32_t g_wF[K_ * 2 * 8 * 32 * 8];   // B fragments

// ---------------- helpers ----------------
__device__ __forceinline__ uint32_t smem_u32(const void* p) {
    uint32_t a;
    asm("{ .reg .u64 t; cvta.to.shared.u64 t, %1; cvt.u32.u64 %0, t; }"
        : "=r"(a) : "l"(p));
    return a;
}
__device__ __forceinline__ uint32_t bf16x2(float hi_elem, float lo_elem) {
    uint32_t r;
    asm("cvt.rn.bf16x2.f32 %0, %1, %2;" : "=r"(r) : "f"(hi_elem), "f"(lo_elem));
    return r;
}
__device__ __forceinline__ void ldm_x4(uint32_t* r, uint32_t addr) {
    asm volatile("ldmatrix.sync.aligned.m8n8.x4.shared.b16 {%0,%1,%2,%3}, [%4];"
                 : "=r"(r[0]), "=r"(r[1]), "=r"(r[2]), "=r"(r[3]) : "r"(addr));
}
__device__ __forceinline__ void mma_bf16(float* c, const uint32_t* a,
                                         const uint32_t* b) {
    asm volatile(
        "mma.sync.aligned.m16n8k16.row.col.f32.bf16.bf16.f32 "
        "{%0,%1,%2,%3}, {%4,%5,%6,%7}, {%8,%9}, {%0,%1,%2,%3};"
        : "+f"(c[0]), "+f"(c[1]), "+f"(c[2]), "+f"(c[3])
        : "r"(a[0]), "r"(a[1]), "r"(a[2]), "r"(a[3]), "r"(b[0]), "r"(b[1]));
}
__device__ __forceinline__ void bar_pair(int id) {
    asm volatile("bar.sync %0, 64;" :: "r"(id) : "memory");
}

// ---------------- prep ----------------
__global__ void prep_kernel(const float* __restrict__ x,
                            const float* __restrict__ w) {
    const int stride = gridDim.x * blockDim.x;
    const int tid = blockIdx.x * blockDim.x + threadIdx.x;

    // x [b][c][p] -> xT [b][p][c]
    for (int i = tid; i < B_ * CIN_ * P_; i += stride) {
        int s = i % P_;
        int c = (i / P_) % CIN_;
        int b = i / (P_ * CIN_);
        g_xT[(b * P_ + s) * CIN_ + c] = x[i];
    }

    // weight [o][c][k] -> mma B fragments: [kt][hl][jg][lane][ks*2+reg]
    for (int i = tid; i < K_ * 2 * 8 * 32 * 8; i += stride) {
        int u    = i & 7;
        int ln   = (i >> 3) & 31;
        int jg   = (i >> 8) & 7;
        int hl   = (i >> 11) & 1;
        int kt   = i >> 12;
        int ks   = u >> 1, reg = u & 1;
        int n = jg * 8 + (ln >> 2);
        int c = ks * 16 + (ln & 3) * 2 + reg * 8;
        float v0 = w[(n * CIN_ + c) * K_ + kt];
        float v1 = w[(n * CIN_ + c + 1) * K_ + kt];
        __nv_bfloat16 h0 = __float2bfloat16(v0);
        __nv_bfloat16 h1 = __float2bfloat16(v1);
        uint32_t valu;
        if (hl == 0) {
            valu = ((uint32_t)__bfloat16_as_ushort(h1) << 16) |
                   (uint32_t)__bfloat16_as_ushort(h0);
        } else {
            __nv_bfloat16 l0 = __float2bfloat16(v0 - __bfloat162float(h0));
            __nv_bfloat16 l1 = __float2bfloat16(v1 - __bfloat162float(h1));
            valu = ((uint32_t)__bfloat16_as_ushort(l1) << 16) |
                   (uint32_t)__bfloat16_as_ushort(l0);
        }
        g_wF[i] = valu;
    }
}

// ---------------- main ----------------
__global__ __launch_bounds__(THREADS, 2)
void deform_hmma_kernel(const float* __restrict__ offset,
                        const float* __restrict__ bias,
                        float* __restrict__ out) {
    extern __shared__ __align__(1024) char smem[];
    const uint32_t sb = smem_u32(smem);

    const int tid  = threadIdx.x;
    const int lane = tid & 31;
    const int warp = tid >> 5;               // 8 warps
    const int blk  = blockIdx.x;
    const int b    = blk >> 7;               // 128 blocks per batch
    const int p0   = (blk & 127) * MTILE;

    const float* offB = offset + (size_t)b * 3 * K_ * P_;
    const char*  xb   = reinterpret_cast<const char*>(g_xT + (size_t)b * P_ * CIN_);

    // sampling role: 8 points per warp
    const int half = lane >> 4;
    const int c4   = lane & 15;
    const int pl_base = warp * 8;
    const char* base2 = xb + (uint32_t)(c4 << 4);
    uint32_t wAoff[8];
#pragma unroll
    for (int i = 0; i < 8; i++) {
        int pl = pl_base + i;
        wAoff[i] = (uint32_t)(pl * 128 + ((c4 * 8) ^ ((pl & 7) << 4)));
    }

    // mma role: warp (mt, nt) owns D[mt*16..+15][nt*32..+31]
    const int mt = warp >> 1, nt = warp & 1;
    const int rowA = mt * 16 + (lane & 15);
    const uint32_t aBaseOff = (uint32_t)(rowA * 128);
    const uint32_t aXor = (uint32_t)((rowA & 7) << 4);
    const uint32_t aKh  = (uint32_t)((lane >> 4) << 4);

    float acc[4][4];
#pragma unroll
    for (int j = 0; j < 4; j++)
#pragma unroll
        for (int q = 0; q < 4; q++) acc[j][q] = 0.f;

    const uint4* gF = reinterpret_cast<const uint4*>(g_wF);

#pragma unroll 1
    for (int kt = 0; kt < K_; kt++) {
        const int buf = kt & 1;
        char* AhP = smem + buf * 16384;
        char* AlP = AhP + 8192;
        const uint32_t AhB = sb + buf * 16384;
        const uint32_t AlB = AhB + 8192;

        // ---- sampling: 8 points per warp ----
        const int kd = kt / 9, kh3 = (kt / 3) % 3, kw3 = kt % 3;
        const float* offk = offB + 3 * kt * P_;

#pragma unroll
        for (int i = 0; i < 8; i++) {
            const int p  = p0 + pl_base + i;
            const int od = p >> 10, oh = (p >> 5) & 31, ow = p & 31;

            float zd = (float)(od - 1 + kd)  + __ldg(offk + p);
            float zh = (float)(oh - 1 + kh3) + __ldg(offk + P_ + p);
            float zw = (float)(ow - 1 + kw3) + __ldg(offk + 2 * P_ + p);

            float fd = floorf(zd); int d0 = (int)fd; float rd = zd - fd;
            float fh = floorf(zh); int h0 = (int)fh; float rh = zh - fh;
            float fw = floorf(zw); int w0 = (int)fw; float rw = zw - fw;

            float wd = half ? (((unsigned)(d0 + 1) < (unsigned)D_) ? rd : 0.f)
                            : (((unsigned)d0 < (unsigned)D_) ? 1.f - rd : 0.f);
            float wh0 = ((unsigned)h0       < (unsigned)H_) ? 1.f - rh : 0.f;
            float wh1 = ((unsigned)(h0 + 1) < (unsigned)H_) ? rh       : 0.f;
            float ww0 = ((unsigned)w0       < (unsigned)W_) ? 1.f - rw : 0.f;
            float ww1 = ((unsigned)(w0 + 1) < (unsigned)W_) ? rw       : 0.f;

            // linear AND-wrap index (wrapped corners carry weight 0)
            const int s0 = (d0 + half) * 1024 + h0 * 32 + w0;
            const uint32_t i0 = ((uint32_t)s0        & 8191u) << 8;
            const uint32_t i1 = ((uint32_t)(s0 + 1)  & 8191u) << 8;
            const uint32_t i2 = ((uint32_t)(s0 + 32) & 8191u) << 8;
            const uint32_t i3 = ((uint32_t)(s0 + 33) & 8191u) << 8;

            const float wdh0 = wd * wh0, wdh1 = wd * wh1;
            const float g0 = wdh0 * ww0, g1 = wdh0 * ww1;
            const float g2 = wdh1 * ww0, g3 = wdh1 * ww1;

            float4 v0 = __ldg(reinterpret_cast<const float4*>(base2 + i0));
            float4 v1 = __ldg(reinterpret_cast<const float4*>(base2 + i1));
            float4 v2 = __ldg(reinterpret_cast<const float4*>(base2 + i2));
            float4 v3 = __ldg(reinterpret_cast<const float4*>(base2 + i3));

            float ax = g0 * v0.x + g1 * v1.x + g2 * v2.x + g3 * v3.x;
            float ay = g0 * v0.y + g1 * v1.y + g2 * v2.y + g3 * v3.y;
            float az = g0 * v0.z + g1 * v1.z + g2 * v2.z + g3 * v3.z;
            float aw = g0 * v0.w + g1 * v1.w + g2 * v2.w + g3 * v3.w;

            ax += __shfl_down_sync(FULL, ax, 16);
            ay += __shfl_down_sync(FULL, ay, 16);
            az += __shfl_down_sync(FULL, az, 16);
            aw += __shfl_down_sync(FULL, aw, 16);

            if (half == 0) {
                uint32_t h01 = bf16x2(ay, ax);       // hi=ch+1, lo=ch+0
                uint32_t h23 = bf16x2(aw, az);
                float hx = __uint_as_float(h01 << 16);
                float hy = __uint_as_float(h01 & 0xffff0000u);
                float hz = __uint_as_float(h23 << 16);
                float hww = __uint_as_float(h23 & 0xffff0000u);
                uint32_t l01 = bf16x2(ay - hy, ax - hx);
                uint32_t l23 = bf16x2(aw - hww, az - hz);
                *reinterpret_cast<uint2*>(AhP + wAoff[i]) = make_uint2(h01, h23);
                *reinterpret_cast<uint2*>(AlP + wAoff[i]) = make_uint2(l01, l23);
            }
        }

        bar_pair(mt + 1);   // warps {2mt, 2mt+1}: produce rows == consume rows

        // ---- A fragments: all 4 K-steps, hi+lo ----
        uint32_t ah[4][4], al[4][4];
#pragma unroll
        for (int ks = 0; ks < 4; ks++) {
            const uint32_t aoff = aBaseOff + (((uint32_t)(ks * 32) + aKh) ^ aXor);
            ldm_x4(ah[ks], AhB + aoff);
            ldm_x4(al[ks], AlB + aoff);
        }

        // ---- B fragments from global (fragment-ordered, L1-hot) + MMA ----
#pragma unroll
        for (int j = 0; j < 4; j++) {
            const size_t hiIdx =
                ((size_t)kt * 16 + (nt * 4 + j)) * 64 + lane * 2;
            uint4 q0 = __ldg(gF + hiIdx);
            uint4 q1 = __ldg(gF + hiIdx + 1);
            uint4 r0 = __ldg(gF + hiIdx + 512);   // lo plane
            uint4 r1 = __ldg(gF + hiIdx + 513);
            uint32_t bh[8] = {q0.x, q0.y, q0.z, q0.w, q1.x, q1.y, q1.z, q1.w};
            uint32_t bl[8] = {r0.x, r0.y, r0.z, r0.w, r1.x, r1.y, r1.z, r1.w};
#pragma unroll
            for (int ks = 0; ks < 4; ks++) {
                mma_bf16(acc[j], ah[ks], &bh[ks * 2]);
                mma_bf16(acc[j], al[ks], &bh[ks * 2]);
                mma_bf16(acc[j], ah[ks], &bl[ks * 2]);
            }
        }
        // A buf reuse at kt+2 ordered by bar_pair at kt+1
    }

    // ---- epilogue: D fragment scatter + bias ----
    const int m = lane >> 2;
    const int p = p0 + mt * 16 + m;
#pragma unroll
    for (int j = 0; j < 4; j++) {
        const int n = nt * 32 + j * 8 + 2 * (lane & 3);
        const float bv0 = __ldg(&bias[n]);
        const float bv1 = __ldg(&bias[n + 1]);
        float* o0 = out + ((size_t)(b * COUT_ + n)) * P_ + p;
        o0[0]      = acc[j][0] + bv0;
        o0[P_]     = acc[j][1] + bv1;
        o0[8]      = acc[j][2] + bv0;
        o0[P_ + 8] = acc[j][3] + bv1;
    }
}

extern "C" void kernel_launch(void* const* d_in, const int* in_sizes, int n_in,
                              void* d_out, int out_size) {
    const float* x      = (const float*)d_in[0];
    const float* offset = (const float*)d_in[1];
    const float* weight = (const float*)d_in[2];
    const float* bias   = (const float*)d_in[3];
    float* out = (float*)d_out;

    cudaFuncSetAttribute(deform_hmma_kernel,
                         cudaFuncAttributeMaxDynamicSharedMemorySize, SM_TOTAL);
    prep_kernel<<<512, 256>>>(x, weight);
    deform_hmma_kernel<<<NBLK, THREADS, SM_TOTAL>>>(offset, bias, out);
}

// round 12
// speedup vs baseline: 2.0562x; 1.0616x over previous
#include <cuda_runtime.h>
#include <cuda_bf16.h>
#include <cstdint>

// Deformable Conv3d via portable HMMA (mma.sync.m16n8k16.bf16, hi/lo split).
// R12: R11 + B fragments stored in two contiguous per-lane planes so every
//      B LDG.128 is warp-contiguous (4 wavefronts, was 8).
//      MTILE=64 / 256 thr / 256 blocks -> 2 independent blocks per SM;
//      no block-wide syncs, only per-warp-pair named barriers.

namespace {
constexpr int B_ = 2, CIN_ = 64, COUT_ = 64, D_ = 8, H_ = 32, W_ = 32, K_ = 27;
constexpr int P_ = D_ * H_ * W_;              // 8192
constexpr int MTILE = 64;
constexpr int THREADS = 256;
constexpr int NBLK = (B_ * P_) / MTILE;       // 256

constexpr int SM_TOTAL = 2 * 16384;           // A: [buf][hi 8K | lo 8K]
constexpr unsigned FULL = 0xffffffffu;
}

__device__ __align__(256) float g_xT[B_ * P_ * CIN_];           // channels-last x
// B fragments, uint4 units: [kt][hl(2)][jg(8)][plane(2)][lane(32)]
__device__ __align__(256) uint32_t g_wF[K_ * 2 * 8 * 2 * 32 * 4];

// ---------------- helpers ----------------
__device__ __forceinline__ uint32_t smem_u32(const void* p) {
    uint32_t a;
    asm("{ .reg .u64 t; cvta.to.shared.u64 t, %1; cvt.u32.u64 %0, t; }"
        : "=r"(a) : "l"(p));
    return a;
}
__device__ __forceinline__ uint32_t bf16x2(float hi_elem, float lo_elem) {
    uint32_t r;
    asm("cvt.rn.bf16x2.f32 %0, %1, %2;" : "=r"(r) : "f"(hi_elem), "f"(lo_elem));
    return r;
}
__device__ __forceinline__ void ldm_x4(uint32_t* r, uint32_t addr) {
    asm volatile("ldmatrix.sync.aligned.m8n8.x4.shared.b16 {%0,%1,%2,%3}, [%4];"
                 : "=r"(r[0]), "=r"(r[1]), "=r"(r[2]), "=r"(r[3]) : "r"(addr));
}
__device__ __forceinline__ void mma_bf16(float* c, const uint32_t* a,
                                         const uint32_t* b) {
    asm volatile(
        "mma.sync.aligned.m16n8k16.row.col.f32.bf16.bf16.f32 "
        "{%0,%1,%2,%3}, {%4,%5,%6,%7}, {%8,%9}, {%0,%1,%2,%3};"
        : "+f"(c[0]), "+f"(c[1]), "+f"(c[2]), "+f"(c[3])
        : "r"(a[0]), "r"(a[1]), "r"(a[2]), "r"(a[3]), "r"(b[0]), "r"(b[1]));
}
__device__ __forceinline__ void bar_pair(int id) {
    asm volatile("bar.sync %0, 64;" :: "r"(id) : "memory");
}

// ---------------- prep ----------------
__global__ void prep_kernel(const float* __restrict__ x,
                            const float* __restrict__ w) {
    const int stride = gridDim.x * blockDim.x;
    const int tid = blockIdx.x * blockDim.x + threadIdx.x;

    // x [b][c][p] -> xT [b][p][c]
    for (int i = tid; i < B_ * CIN_ * P_; i += stride) {
        int s = i % P_;
        int c = (i / P_) % CIN_;
        int b = i / (P_ * CIN_);
        g_xT[(b * P_ + s) * CIN_ + c] = x[i];
    }

    // weight [o][c][k] -> B fragments [kt][hl][jg][pl][lane][uu]
    for (int i = tid; i < K_ * 2 * 8 * 2 * 32 * 4; i += stride) {
        int uu   = i & 3;
        int ln   = (i >> 2) & 31;
        int pl   = (i >> 7) & 1;
        int jg   = (i >> 8) & 7;
        int hl   = (i >> 11) & 1;
        int kt   = i >> 12;
        int u    = pl * 4 + uu;            // ks*2 + reg
        int ks   = u >> 1, reg = u & 1;
        int n = jg * 8 + (ln >> 2);
        int c = ks * 16 + (ln & 3) * 2 + reg * 8;
        float v0 = w[(n * CIN_ + c) * K_ + kt];
        float v1 = w[(n * CIN_ + c + 1) * K_ + kt];
        __nv_bfloat16 h0 = __float2bfloat16(v0);
        __nv_bfloat16 h1 = __float2bfloat16(v1);
        uint32_t valu;
        if (hl == 0) {
            valu = ((uint32_t)__bfloat16_as_ushort(h1) << 16) |
                   (uint32_t)__bfloat16_as_ushort(h0);
        } else {
            __nv_bfloat16 l0 = __float2bfloat16(v0 - __bfloat162float(h0));
            __nv_bfloat16 l1 = __float2bfloat16(v1 - __bfloat162float(h1));
            valu = ((uint32_t)__bfloat16_as_ushort(l1) << 16) |
                   (uint32_t)__bfloat16_as_ushort(l0);
        }
        g_wF[i] = valu;
    }
}

// ---------------- main ----------------
__global__ __launch_bounds__(THREADS, 2)
void deform_hmma_kernel(const float* __restrict__ offset,
                        const float* __restrict__ bias,
                        float* __restrict__ out) {
    extern __shared__ __align__(1024) char smem[];
    const uint32_t sb = smem_u32(smem);

    const int tid  = threadIdx.x;
    const int lane = tid & 31;
    const int warp = tid >> 5;               // 8 warps
    const int blk  = blockIdx.x;
    const int b    = blk >> 7;
    const int p0   = (blk & 127) * MTILE;

    const float* offB = offset + (size_t)b * 3 * K_ * P_;
    const char*  xb   = reinterpret_cast<const char*>(g_xT + (size_t)b * P_ * CIN_);

    // sampling role: 8 points per warp
    const int half = lane >> 4;
    const int c4   = lane & 15;
    const int pl_base = warp * 8;
    const char* base2 = xb + (uint32_t)(c4 << 4);
    uint32_t wAoff[8];
#pragma unroll
    for (int i = 0; i < 8; i++) {
        int pl = pl_base + i;
        wAoff[i] = (uint32_t)(pl * 128 + ((c4 * 8) ^ ((pl & 7) << 4)));
    }

    // mma role: warp (mt, nt) owns D[mt*16..+15][nt*32..+31]
    const int mt = warp >> 1, nt = warp & 1;
    const int rowA = mt * 16 + (lane & 15);
    const uint32_t aBaseOff = (uint32_t)(rowA * 128);
    const uint32_t aXor = (uint32_t)((rowA & 7) << 4);
    const uint32_t aKh  = (uint32_t)((lane >> 4) << 4);

    float acc[4][4];
#pragma unroll
    for (int j = 0; j < 4; j++)
#pragma unroll
        for (int q = 0; q < 4; q++) acc[j][q] = 0.f;

    const uint4* gF = reinterpret_cast<const uint4*>(g_wF);

#pragma unroll 1
    for (int kt = 0; kt < K_; kt++) {
        const int buf = kt & 1;
        char* AhP = smem + buf * 16384;
        char* AlP = AhP + 8192;
        const uint32_t AhB = sb + buf * 16384;
        const uint32_t AlB = AhB + 8192;

        // ---- sampling: 8 points per warp ----
        const int kd = kt / 9, kh3 = (kt / 3) % 3, kw3 = kt % 3;
        const float* offk = offB + 3 * kt * P_;

#pragma unroll
        for (int i = 0; i < 8; i++) {
            const int p  = p0 + pl_base + i;
            const int od = p >> 10, oh = (p >> 5) & 31, ow = p & 31;

            float zd = (float)(od - 1 + kd)  + __ldg(offk + p);
            float zh = (float)(oh - 1 + kh3) + __ldg(offk + P_ + p);
            float zw = (float)(ow - 1 + kw3) + __ldg(offk + 2 * P_ + p);

            float fd = floorf(zd); int d0 = (int)fd; float rd = zd - fd;
            float fh = floorf(zh); int h0 = (int)fh; float rh = zh - fh;
            float fw = floorf(zw); int w0 = (int)fw; float rw = zw - fw;

            float wd = half ? (((unsigned)(d0 + 1) < (unsigned)D_) ? rd : 0.f)
                            : (((unsigned)d0 < (unsigned)D_) ? 1.f - rd : 0.f);
            float wh0 = ((unsigned)h0       < (unsigned)H_) ? 1.f - rh : 0.f;
            float wh1 = ((unsigned)(h0 + 1) < (unsigned)H_) ? rh       : 0.f;
            float ww0 = ((unsigned)w0       < (unsigned)W_) ? 1.f - rw : 0.f;
            float ww1 = ((unsigned)(w0 + 1) < (unsigned)W_) ? rw       : 0.f;

            // linear AND-wrap index (wrapped corners carry weight 0)
            const int s0 = (d0 + half) * 1024 + h0 * 32 + w0;
            const uint32_t i0 = ((uint32_t)s0        & 8191u) << 8;
            const uint32_t i1 = ((uint32_t)(s0 + 1)  & 8191u) << 8;
            const uint32_t i2 = ((uint32_t)(s0 + 32) & 8191u) << 8;
            const uint32_t i3 = ((uint32_t)(s0 + 33) & 8191u) << 8;

            const float wdh0 = wd * wh0, wdh1 = wd * wh1;
            const float g0 = wdh0 * ww0, g1 = wdh0 * ww1;
            const float g2 = wdh1 * ww0, g3 = wdh1 * ww1;

            float4 v0 = __ldg(reinterpret_cast<const float4*>(base2 + i0));
            float4 v1 = __ldg(reinterpret_cast<const float4*>(base2 + i1));
            float4 v2 = __ldg(reinterpret_cast<const float4*>(base2 + i2));
            float4 v3 = __ldg(reinterpret_cast<const float4*>(base2 + i3));

            float ax = g0 * v0.x + g1 * v1.x + g2 * v2.x + g3 * v3.x;
            float ay = g0 * v0.y + g1 * v1.y + g2 * v2.y + g3 * v3.y;
            float az = g0 * v0.z + g1 * v1.z + g2 * v2.z + g3 * v3.z;
            float aw = g0 * v0.w + g1 * v1.w + g2 * v2.w + g3 * v3.w;

            ax += __shfl_down_sync(FULL, ax, 16);
            ay += __shfl_down_sync(FULL, ay, 16);
            az += __shfl_down_sync(FULL, az, 16);
            aw += __shfl_down_sync(FULL, aw, 16);

            if (half == 0) {
                uint32_t h01 = bf16x2(ay, ax);       // hi=ch+1, lo=ch+0
                uint32_t h23 = bf16x2(aw, az);
                float hx = __uint_as_float(h01 << 16);
                float hy = __uint_as_float(h01 & 0xffff0000u);
                float hz = __uint_as_float(h23 << 16);
                float hww = __uint_as_float(h23 & 0xffff0000u);
                uint32_t l01 = bf16x2(ay - hy, ax - hx);
                uint32_t l23 = bf16x2(aw - hww, az - hz);
                *reinterpret_cast<uint2*>(AhP + wAoff[i]) = make_uint2(h01, h23);
                *reinterpret_cast<uint2*>(AlP + wAoff[i]) = make_uint2(l01, l23);
            }
        }

        bar_pair(mt + 1);   // warps {2mt, 2mt+1}: produce rows == consume rows

        // ---- A fragments: all 4 K-steps, hi+lo ----
        uint32_t ah[4][4], al[4][4];
#pragma unroll
        for (int ks = 0; ks < 4; ks++) {
            const uint32_t aoff = aBaseOff + (((uint32_t)(ks * 32) + aKh) ^ aXor);
            ldm_x4(ah[ks], AhB + aoff);
            ldm_x4(al[ks], AlB + aoff);
        }

        // ---- B fragments from global (contiguous per-lane planes) + MMA ----
        // uint4 index: kt*1024 + hl*512 + jg*64 + pl*32 + lane
#pragma unroll
        for (int j = 0; j < 4; j++) {
            const size_t idx = (size_t)kt * 1024 + (size_t)(nt * 4 + j) * 64 + lane;
            uint4 q0 = __ldg(gF + idx);           // hi, plane0 (ks0-1)
            uint4 q1 = __ldg(gF + idx + 32);      // hi, plane1 (ks2-3)
            uint4 r0 = __ldg(gF + idx + 512);     // lo, plane0
            uint4 r1 = __ldg(gF + idx + 544);     // lo, plane1
            uint32_t bh[8] = {q0.x, q0.y, q0.z, q0.w, q1.x, q1.y, q1.z, q1.w};
            uint32_t bl[8] = {r0.x, r0.y, r0.z, r0.w, r1.x, r1.y, r1.z, r1.w};
#pragma unroll
            for (int ks = 0; ks < 4; ks++) {
                mma_bf16(acc[j], ah[ks], &bh[ks * 2]);
                mma_bf16(acc[j], al[ks], &bh[ks * 2]);
                mma_bf16(acc[j], ah[ks], &bl[ks * 2]);
            }
        }
        // A buf reuse at kt+2 ordered by bar_pair at kt+1
    }

    // ---- epilogue: D fragment scatter + bias ----
    const int m = lane >> 2;
    const int p = p0 + mt * 16 + m;
#pragma unroll
    for (int j = 0; j < 4; j++) {
        const int n = nt * 32 + j * 8 + 2 * (lane & 3);
        const float bv0 = __ldg(&bias[n]);
        const float bv1 = __ldg(&bias[n + 1]);
        float* o0 = out + ((size_t)(b * COUT_ + n)) * P_ + p;
        o0[0]      = acc[j][0] + bv0;
        o0[P_]     = acc[j][1] + bv1;
        o0[8]      = acc[j][2] + bv0;
        o0[P_ + 8] = acc[j][3] + bv1;
    }
}

extern "C" void kernel_launch(void* const* d_in, const int* in_sizes, int n_in,
                              void* d_out, int out_size) {
    const float* x      = (const float*)d_in[0];
    const float* offset = (const float*)d_in[1];
    const float* weight = (const float*)d_in[2];
    const float* bias   = (const float*)d_in[3];
    float* out = (float*)d_out;

    cudaFuncSetAttribute(deform_hmma_kernel,
                         cudaFuncAttributeMaxDynamicSharedMemorySize, SM_TOTAL);
    prep_kernel<<<256, 256>>>(x, weight);
    deform_hmma_kernel<<<NBLK, THREADS, SM_TOTAL>>>(offset, bias, out);
}